// round 14
// baseline (speedup 1.0000x reference)
#include <cuda_runtime.h>
#include <cuda_fp16.h>
#include <cstdint>

// Problem constants
#define BATCH 4
#define SEQ 4096
#define DMODEL 1024
#define NHEAD 16
#define HDIM 64
#define MROWS (BATCH * SEQ)        // 16384
#define BH (BATCH * NHEAD)         // 64
#define KV_CHUNKS 32               // 128-row chunks per batch

// Scratch (device globals; no cudaMalloc allowed)
__device__ __half g_X[MROWS * DMODEL];
__device__ __half g_W[3][DMODEL * DMODEL];       // fp16, TRANSPOSED Wq,Wk,Wv [n,k]
__device__ __half g_Q[MROWS * DMODEL];
__device__ __half g_K[MROWS * DMODEL];
__device__ __half g_V[MROWS * DMODEL];
__device__ float  g_KVp[KV_CHUNKS * BH * HDIM * HDIM];
__device__ float  g_KV[BH * HDIM * HDIM];
__device__ __half g_M[BATCH * DMODEL * DMODEL];  // M_bT[b][n][dh], fp16

// ---------------------------------------------------------------------------
// Helpers
// ---------------------------------------------------------------------------
__device__ __forceinline__ void mma_f16(float c[4], const uint32_t a[4], const uint32_t b[2]) {
    asm volatile(
        "mma.sync.aligned.m16n8k16.row.col.f32.f16.f16.f32 "
        "{%0,%1,%2,%3}, {%4,%5,%6,%7}, {%8,%9}, {%0,%1,%2,%3};\n"
        : "+f"(c[0]), "+f"(c[1]), "+f"(c[2]), "+f"(c[3])
        : "r"(a[0]), "r"(a[1]), "r"(a[2]), "r"(a[3]), "r"(b[0]), "r"(b[1]));
}

__device__ __forceinline__ void ldsm_x4(uint32_t& r0, uint32_t& r1, uint32_t& r2, uint32_t& r3,
                                        uint32_t addr) {
    asm volatile("ldmatrix.sync.aligned.m8n8.x4.shared.b16 {%0,%1,%2,%3}, [%4];"
                 : "=r"(r0), "=r"(r1), "=r"(r2), "=r"(r3) : "r"(addr));
}

__device__ __forceinline__ void ldsm_x4_t(uint32_t& r0, uint32_t& r1, uint32_t& r2, uint32_t& r3,
                                          uint32_t addr) {
    asm volatile("ldmatrix.sync.aligned.m8n8.x4.trans.shared.b16 {%0,%1,%2,%3}, [%4];"
                 : "=r"(r0), "=r"(r1), "=r"(r2), "=r"(r3) : "r"(addr));
}

__device__ __forceinline__ uint32_t smem_u32(const void* p) {
    return (uint32_t)__cvta_generic_to_shared(p);
}

__device__ __forceinline__ void cp_async16(void* smem, const void* gmem) {
    uint32_t s = smem_u32(smem);
    asm volatile("cp.async.cg.shared.global [%0], [%1], 16;\n" :: "r"(s), "l"(gmem));
}
__device__ __forceinline__ void cp_commit() { asm volatile("cp.async.commit_group;\n"); }
template<int N>
__device__ __forceinline__ void cp_wait() { asm volatile("cp.async.wait_group %0;\n" :: "n"(N)); }

// ---------------------------------------------------------------------------
// Pre-round x to fp16
// ---------------------------------------------------------------------------
__global__ void __launch_bounds__(256)
round_fp16(const float* __restrict__ in, __half* __restrict__ out, int n4) {
    int i = blockIdx.x * blockDim.x + threadIdx.x;
    if (i >= n4) return;
    float4 v = ((const float4*)in)[i];
    ((__half2*)out)[2 * i]     = __floats2half2_rn(v.x, v.y);
    ((__half2*)out)[2 * i + 1] = __floats2half2_rn(v.z, v.w);
}

// Transpose + fp16 round: out[n,k] = fp16(in[k,n]); 1024x1024
__global__ void __launch_bounds__(256)
transpose_fp16(const float* __restrict__ in, __half* __restrict__ out) {
    __shared__ float t[32][33];
    int bx = blockIdx.x * 32, by = blockIdx.y * 32;
    int tx = threadIdx.x, ty = threadIdx.y;
    #pragma unroll
    for (int j = 0; j < 32; j += 8)
        t[ty + j][tx] = in[(size_t)(by + ty + j) * DMODEL + bx + tx];
    __syncthreads();
    #pragma unroll
    for (int j = 0; j < 32; j += 8)
        out[(size_t)(bx + ty + j) * DMODEL + by + tx] = __float2half_rn(t[tx][ty + j]);
}

// ---------------------------------------------------------------------------
// FP16 GEMM (m16n8k16, fp32 accumulate), ldmatrix fragments.
// C[M,N] = A[M,K] @ Bt[N,K]^T + bias
// MODE: 0 = plain fp32 out, 3 = softmax fp16 out, 4 = plain fp16 out.
// ---------------------------------------------------------------------------
#define BM 128
#define BN 128
#define BKH 32
#define STAGES 3
#define TSTRH 40

struct SmemPipeH {
    __half As[STAGES][BM][TSTRH];
    __half Bs[STAGES][BN][TSTRH];
};

template<int MODE>
__global__ void __launch_bounds__(128, 2)
gemm_h(const __half* __restrict__ A, const __half* __restrict__ Bt,
       const float* __restrict__ bias, void* __restrict__ Cv,
       int N, int K) {
    extern __shared__ char smem_raw[];
    SmemPipeH& sp = *reinterpret_cast<SmemPipeH*>(smem_raw);

    float*  Cf = (float*)Cv;
    __half* Ch = (__half*)Cv;

    const int tid  = threadIdx.x;
    const int warp = tid >> 5;
    const int lane = tid & 31;
    const int g  = lane >> 2;
    const int tg = lane & 3;
    const int wm = (warp >> 1) * 64;
    const int wn = (warp & 1) * 64;
    const int bm = blockIdx.y * BM;
    const int bn = blockIdx.x * BN;

    const int a_row  = lane & 15;
    const int a_koff = (lane >> 4) * 8;
    const int b_row  = (lane & 7) + ((lane >> 4) << 3);
    const int b_koff = ((lane >> 3) & 1) * 8;

    const int T = K / BKH;   // 32

    auto load_stage = [&](int kt, int st) {
        #pragma unroll
        for (int i = 0; i < 4; i++) {
            int f = tid + i * 128;
            int r = f >> 2, c = (f & 3) * 8;
            cp_async16(&sp.As[st][r][c], &A[(size_t)(bm + r) * K + kt + c]);
        }
        #pragma unroll
        for (int i = 0; i < 4; i++) {
            int f = tid + i * 128;
            int r = f >> 2, c = (f & 3) * 8;
            cp_async16(&sp.Bs[st][r][c], &Bt[(size_t)(bn + r) * K + kt + c]);
        }
        cp_commit();
    };

    float acc[4][8][4] = {};

    load_stage(0, 0);
    load_stage(BKH, 1);

    for (int t = 0; t < T; t++) {
        if (t > 0) __syncthreads();
        if (t + 2 < T) {
            load_stage((t + 2) * BKH, (t + 2) % STAGES);
            cp_wait<2>();
        } else if (t + 1 < T) {
            cp_wait<1>();
        } else {
            cp_wait<0>();
        }
        __syncthreads();

        const int st = t % STAGES;
        #pragma unroll
        for (int k0 = 0; k0 < BKH; k0 += 16) {
            uint32_t af[4][4];
            uint32_t bf[8][2];
            #pragma unroll
            for (int mi = 0; mi < 4; mi++) {
                uint32_t addr = smem_u32(&sp.As[st][wm + mi * 16 + a_row][k0 + a_koff]);
                ldsm_x4(af[mi][0], af[mi][1], af[mi][2], af[mi][3], addr);
            }
            #pragma unroll
            for (int nb = 0; nb < 4; nb++) {
                uint32_t addr = smem_u32(&sp.Bs[st][wn + nb * 16 + b_row][k0 + b_koff]);
                ldsm_x4(bf[2*nb][0], bf[2*nb][1], bf[2*nb+1][0], bf[2*nb+1][1], addr);
            }
            #pragma unroll
            for (int mi = 0; mi < 4; mi++)
                #pragma unroll
                for (int ni = 0; ni < 8; ni++)
                    mma_f16(acc[mi][ni], af[mi], bf[ni]);
        }
    }

    if (MODE == 0 || MODE == 4) {
        #pragma unroll
        for (int mi = 0; mi < 4; mi++) {
            int row = bm + wm + mi * 16 + g;
            #pragma unroll
            for (int ni = 0; ni < 8; ni++) {
                int col = bn + wn + ni * 8 + tg * 2;
                float b0 = bias[col], b1 = bias[col + 1];
                if (MODE == 4) {
                    *(__half2*)&Ch[(size_t)row * N + col] =
                        __floats2half2_rn(acc[mi][ni][0] + b0, acc[mi][ni][1] + b1);
                    *(__half2*)&Ch[(size_t)(row + 8) * N + col] =
                        __floats2half2_rn(acc[mi][ni][2] + b0, acc[mi][ni][3] + b1);
                } else {
                    *(float2*)&Cf[(size_t)row * N + col] =
                        make_float2(acc[mi][ni][0] + b0, acc[mi][ni][1] + b1);
                    *(float2*)&Cf[(size_t)(row + 8) * N + col] =
                        make_float2(acc[mi][ni][2] + b0, acc[mi][ni][3] + b1);
                }
            }
        }
    } else {
        float bia[8][2];
        #pragma unroll
        for (int ni = 0; ni < 8; ni++) {
            int col = bn + wn + ni * 8 + tg * 2;
            bia[ni][0] = bias[col];
            bia[ni][1] = bias[col + 1];
        }
        #pragma unroll
        for (int mi = 0; mi < 4; mi++) {
            #pragma unroll
            for (int j = 0; j < 2; j++) {
                float v[16];
                #pragma unroll
                for (int ni = 0; ni < 8; ni++) {
                    v[2*ni]   = acc[mi][ni][2*j]   + bia[ni][0];
                    v[2*ni+1] = acc[mi][ni][2*j+1] + bia[ni][1];
                }
                float m = v[0];
                #pragma unroll
                for (int i = 1; i < 16; i++) m = fmaxf(m, v[i]);
                m = fmaxf(m, __shfl_xor_sync(0xffffffffu, m, 1));
                m = fmaxf(m, __shfl_xor_sync(0xffffffffu, m, 2));
                float s = 0.f;
                #pragma unroll
                for (int i = 0; i < 16; i++) { v[i] = __expf(v[i] - m); s += v[i]; }
                s += __shfl_xor_sync(0xffffffffu, s, 1);
                s += __shfl_xor_sync(0xffffffffu, s, 2);
                float inv = 1.f / s;
                int row = bm + wm + mi * 16 + g + j * 8;
                #pragma unroll
                for (int ni = 0; ni < 8; ni++) {
                    int col = bn + wn + ni * 8 + tg * 2;
                    *(__half2*)&Ch[(size_t)row * N + col] =
                        __floats2half2_rn(v[2*ni] * inv, v[2*ni+1] * inv);
                }
            }
        }
    }
}

// ---------------------------------------------------------------------------
// Tensor-core KV partials; bh0 selects the bh range (per-batch split).
// ---------------------------------------------------------------------------
#define KVSTR 72

__global__ void __launch_bounds__(128)
kv_mma(const __half* __restrict__ Kh, const __half* __restrict__ Vh,
       float* __restrict__ KVp, int bh0) {
    __shared__ __align__(16) char smem[2 * 128 * KVSTR * 2];
    __half (*Ks)[KVSTR] = reinterpret_cast<__half(*)[KVSTR]>(smem);
    __half (*Vs)[KVSTR] = reinterpret_cast<__half(*)[KVSTR]>(smem + 128 * KVSTR * 2);
    float  (*buf)[72]   = reinterpret_cast<float(*)[72]>(smem);

    const int chunk = blockIdx.x;
    const int bh = blockIdx.y + bh0;
    const int b = bh >> 4, h = bh & 15;
    const int tid = threadIdx.x, warp = tid >> 5, lane = tid & 31;
    const int g = lane >> 2, tg = lane & 3;

    const size_t rowbase = ((size_t)b * SEQ + chunk * 128) * DMODEL + h * 64;
    #pragma unroll
    for (int i = 0; i < 8; i++) {
        int f = tid + i * 128;
        int r = f >> 3, c = (f & 7) * 8;
        cp_async16(&Ks[r][c], &Kh[rowbase + (size_t)r * DMODEL + c]);
    }
    #pragma unroll
    for (int i = 0; i < 8; i++) {
        int f = tid + i * 128;
        int r = f >> 3, c = (f & 7) * 8;
        cp_async16(&Vs[r][c], &Vh[rowbase + (size_t)r * DMODEL + c]);
    }
    cp_commit(); cp_wait<0>();
    __syncthreads();

    const int a_srow = (lane & 7) + ((lane >> 4) << 3);
    const int a_doff = ((lane >> 3) & 1) * 8;
    const int b_srow = (lane & 7) + (((lane >> 3) & 1) << 3);
    const int b_eoff = (lane >> 4) * 8;

    float acc[4][8][4] = {};
    const int s0 = warp * 32;
    #pragma unroll
    for (int ks = 0; ks < 2; ks++) {
        const int sb = s0 + ks * 16;
        uint32_t af[4][4];
        uint32_t bf[8][2];
        #pragma unroll
        for (int mi = 0; mi < 4; mi++) {
            uint32_t addr = smem_u32(&Ks[sb + a_srow][mi * 16 + a_doff]);
            ldsm_x4_t(af[mi][0], af[mi][1], af[mi][2], af[mi][3], addr);
        }
        #pragma unroll
        for (int nb = 0; nb < 4; nb++) {
            uint32_t addr = smem_u32(&Vs[sb + b_srow][nb * 16 + b_eoff]);
            ldsm_x4_t(bf[2*nb][0], bf[2*nb][1], bf[2*nb+1][0], bf[2*nb+1][1], addr);
        }
        #pragma unroll
        for (int mi = 0; mi < 4; mi++)
            #pragma unroll
            for (int ni = 0; ni < 8; ni++)
                mma_f16(acc[mi][ni], af[mi], bf[ni]);
    }
    __syncthreads();

    for (int w = 0; w < 4; w++) {
        if (warp == w) {
            #pragma unroll
            for (int mi = 0; mi < 4; mi++) {
                #pragma unroll
                for (int ni = 0; ni < 8; ni++) {
                    int r = mi * 16 + g;
                    int c = ni * 8 + tg * 2;
                    if (w == 0) {
                        buf[r][c]       = acc[mi][ni][0];
                        buf[r][c + 1]   = acc[mi][ni][1];
                        buf[r+8][c]     = acc[mi][ni][2];
                        buf[r+8][c + 1] = acc[mi][ni][3];
                    } else {
                        buf[r][c]       += acc[mi][ni][0];
                        buf[r][c + 1]   += acc[mi][ni][1];
                        buf[r+8][c]     += acc[mi][ni][2];
                        buf[r+8][c + 1] += acc[mi][ni][3];
                    }
                }
            }
        }
        __syncthreads();
    }

    float* out = KVp + ((size_t)chunk * BH + bh) * (HDIM * HDIM);
    #pragma unroll
    for (int i = 0; i < 8; i++) {
        int f = tid + i * 128;
        int r = f >> 4, c = (f & 15) * 4;
        float4 v = *(const float4*)&buf[r][c];
        *(float4*)&out[r * 64 + c] = v;
    }
}

// reduce over chunks for bh in [bh0, bh0+nbh)
__global__ void __launch_bounds__(256)
kv_reduce(const float* __restrict__ KVp, float* __restrict__ KV, int bh0, int nbh) {
    int idx = blockIdx.x * blockDim.x + threadIdx.x;
    if (idx >= nbh * HDIM * HDIM) return;
    int gidx = bh0 * HDIM * HDIM + idx;
    float s = 0.f;
    #pragma unroll
    for (int c = 0; c < KV_CHUNKS; c++)
        s += KVp[(size_t)c * BH * HDIM * HDIM + gidx];
    KV[gidx] = s;
}

// ---------------------------------------------------------------------------
// Fold Wo into KV for batch b0:  M_bT[b0][n][64h+d]
// ---------------------------------------------------------------------------
__global__ void __launch_bounds__(256)
fold_wo(const float* __restrict__ KV, const float* __restrict__ Wo,
        __half* __restrict__ Mt, int b0) {
    __shared__ float KVs[64][65];
    __shared__ float Wos[64][65];
    const int nt = blockIdx.x * 64;
    const int h  = blockIdx.y;
    const int b  = b0;
    const int tid = threadIdx.x;

    const float* kvsrc = KV + ((size_t)(b * NHEAD + h)) * (HDIM * HDIM);
    #pragma unroll
    for (int i = 0; i < 4; i++) {
        int f = tid + i * 256;
        int r = f >> 4, c = (f & 15) * 4;
        float4 v = *(const float4*)&kvsrc[r * 64 + c];
        KVs[r][c] = v.x; KVs[r][c+1] = v.y; KVs[r][c+2] = v.z; KVs[r][c+3] = v.w;
    }
    #pragma unroll
    for (int i = 0; i < 4; i++) {
        int f = tid + i * 256;
        int r = f >> 4, c = (f & 15) * 4;
        float4 v = *(const float4*)&Wo[(size_t)(h * 64 + r) * DMODEL + nt + c];
        Wos[r][c] = v.x; Wos[r][c+1] = v.y; Wos[r][c+2] = v.z; Wos[r][c+3] = v.w;
    }
    __syncthreads();

    const int n  = tid >> 2;
    const int d0 = (tid & 3) * 16;
    float acc[16] = {};
    #pragma unroll 8
    for (int e = 0; e < 64; e++) {
        float w = Wos[e][n];
        #pragma unroll
        for (int i = 0; i < 16; i++)
            acc[i] += KVs[d0 + i][e] * w;
    }
    __half* dst = Mt + (size_t)b * DMODEL * DMODEL + (size_t)(nt + n) * DMODEL + h * 64 + d0;
    #pragma unroll
    for (int i = 0; i < 16; i++) dst[i] = __float2half_rn(acc[i]);
}

// ---------------------------------------------------------------------------
// Launch: R12 skeleton (3 streams) + per-batch chain/final pipeline.
// s2: transposeK, K GEMM, then chain(b)=kv_mma/reduce/fold per batch (evM[b])
// s3: transposeV, V GEMM (evV), then finals for b=1,3
// main: round, transposeQ, Q GEMM (evQ), finals for b=0,2; joins s3 at end
// ---------------------------------------------------------------------------
extern "C" void kernel_launch(void* const* d_in, const int* in_sizes, int n_in,
                              void* d_out, int out_size) {
    const float* x  = (const float*)d_in[0];
    const float* Wq = (const float*)d_in[1];
    const float* bq = (const float*)d_in[2];
    const float* Wk = (const float*)d_in[3];
    const float* bk = (const float*)d_in[4];
    const float* Wv = (const float*)d_in[5];
    const float* bv = (const float*)d_in[6];
    const float* Wo = (const float*)d_in[7];
    const float* bo = (const float*)d_in[8];
    float* out = (float*)d_out;

    __half *X, *W, *Q, *K, *V, *Mt;
    float *KVp, *KV;
    cudaGetSymbolAddress((void**)&X,   g_X);
    cudaGetSymbolAddress((void**)&W,   g_W);
    cudaGetSymbolAddress((void**)&Q,   g_Q);
    cudaGetSymbolAddress((void**)&K,   g_K);
    cudaGetSymbolAddress((void**)&V,   g_V);
    cudaGetSymbolAddress((void**)&KVp, g_KVp);
    cudaGetSymbolAddress((void**)&KV,  g_KV);
    cudaGetSymbolAddress((void**)&Mt,  g_M);

    __half* Wqt = W;
    __half* Wkt = W + (size_t)DMODEL * DMODEL;
    __half* Wvt = W + 2 * (size_t)DMODEL * DMODEL;

    const int smem_bytes = (int)sizeof(SmemPipeH);   // 61,440 B
    static cudaStream_t s2 = nullptr, s3 = nullptr;
    static cudaEvent_t evX, evV, evQ, evJ;
    static cudaEvent_t evM[BATCH];
    if (!s2) {
        cudaFuncSetAttribute(gemm_h<3>, cudaFuncAttributeMaxDynamicSharedMemorySize, smem_bytes);
        cudaFuncSetAttribute(gemm_h<4>, cudaFuncAttributeMaxDynamicSharedMemorySize, smem_bytes);
        cudaFuncSetAttribute(gemm_h<0>, cudaFuncAttributeMaxDynamicSharedMemorySize, smem_bytes);
        int pLeast, pGreatest;
        cudaDeviceGetStreamPriorityRange(&pLeast, &pGreatest);
        cudaStreamCreateWithPriority(&s2, cudaStreamNonBlocking, pGreatest);
        cudaStreamCreateWithPriority(&s3, cudaStreamNonBlocking, pGreatest);
        cudaEventCreateWithFlags(&evX, cudaEventDisableTiming);
        cudaEventCreateWithFlags(&evV, cudaEventDisableTiming);
        cudaEventCreateWithFlags(&evQ, cudaEventDisableTiming);
        cudaEventCreateWithFlags(&evJ, cudaEventDisableTiming);
        for (int b = 0; b < BATCH; b++)
            cudaEventCreateWithFlags(&evM[b], cudaEventDisableTiming);
    }

    dim3 tgrid(32, 32), tblk(32, 8);
    dim3 ggrid (DMODEL / BN, MROWS / BM);        // (8, 128) full GEMM
    dim3 ggridB(DMODEL / BN, SEQ / BM);          // (8, 32)  per-batch final
    const int n4x = MROWS * DMODEL / 4;
    const size_t BOFF = (size_t)SEQ * DMODEL;    // rows per batch
    const size_t MOFF = (size_t)DMODEL * DMODEL; // Mt per batch

    // prologue
    round_fp16<<<(n4x + 255) / 256, 256>>>(x, X, n4x);
    cudaEventRecord(evX, 0);
    transpose_fp16<<<tgrid, tblk, 0, s2>>>(Wk, Wkt);
    transpose_fp16<<<tgrid, tblk, 0, s3>>>(Wv, Wvt);
    transpose_fp16<<<tgrid, tblk>>>(Wq, Wqt);

    // projections, fully concurrent (R12 schedule)
    cudaStreamWaitEvent(s2, evX, 0);
    gemm_h<3><<<ggrid, 128, smem_bytes, s2>>>(X, Wkt, bk, K, DMODEL, DMODEL);

    cudaStreamWaitEvent(s3, evX, 0);
    gemm_h<4><<<ggrid, 128, smem_bytes, s3>>>(X, Wvt, bv, V, DMODEL, DMODEL);
    cudaEventRecord(evV, s3);

    gemm_h<3><<<ggrid, 128, smem_bytes>>>(X, Wqt, bq, Q, DMODEL, DMODEL);
    cudaEventRecord(evQ, 0);

    // per-batch kv chains on s2 (after K via stream order, V via event)
    cudaStreamWaitEvent(s2, evV, 0);
    for (int b = 0; b < BATCH; b++) {
        kv_mma<<<dim3(KV_CHUNKS, NHEAD), 128, 0, s2>>>(K, V, KVp, b * NHEAD);
        kv_reduce<<<(NHEAD * HDIM * HDIM + 255) / 256, 256, 0, s2>>>(KVp, KV, b * NHEAD, NHEAD);
        fold_wo<<<dim3(16, NHEAD), 256, 0, s2>>>(KV, Wo, Mt, b);
        cudaEventRecord(evM[b], s2);
    }

    // per-batch finals, alternating main / s3 for backfill
    for (int b = 0; b < BATCH; b++) {
        cudaStream_t fs = (b & 1) ? s3 : (cudaStream_t)0;
        if (b & 1) cudaStreamWaitEvent(s3, evQ, 0);
        cudaStreamWaitEvent(fs, evM[b], 0);
        gemm_h<0><<<ggridB, 128, smem_bytes, fs>>>(Q + b * BOFF, Mt + b * MOFF, bo,
                                                   out + b * BOFF, DMODEL, DMODEL);
    }

    // join s3's finals into main stream
    cudaEventRecord(evJ, s3);
    cudaStreamWaitEvent(0, evJ, 0);
}

// round 15
// speedup vs baseline: 1.1617x; 1.1617x over previous
#include <cuda_runtime.h>
#include <cuda_fp16.h>
#include <cstdint>

// Problem constants
#define BATCH 4
#define SEQ 4096
#define DMODEL 1024
#define NHEAD 16
#define HDIM 64
#define MROWS (BATCH * SEQ)        // 16384
#define BH (BATCH * NHEAD)         // 64
#define KV_CHUNKS 8                // 512-row chunks per batch
#define SUBS 4                     // 128-row sub-chunks per chunk

// Scratch (device globals; no cudaMalloc allowed)
__device__ __half g_X[MROWS * DMODEL];
__device__ __half g_W[3][DMODEL * DMODEL];       // fp16, TRANSPOSED Wq,Wk,Wv [n,k]
__device__ __half g_Q[MROWS * DMODEL];
__device__ __half g_K[MROWS * DMODEL];
__device__ __half g_V[MROWS * DMODEL];
__device__ float  g_KVp[KV_CHUNKS * BH * HDIM * HDIM];
__device__ float  g_KV[BH * HDIM * HDIM];
__device__ __half g_M[BATCH * DMODEL * DMODEL];  // M_bT[b][n][dh], fp16

// ---------------------------------------------------------------------------
// Helpers
// ---------------------------------------------------------------------------
__device__ __forceinline__ void mma_f16(float c[4], const uint32_t a[4], const uint32_t b[2]) {
    asm volatile(
        "mma.sync.aligned.m16n8k16.row.col.f32.f16.f16.f32 "
        "{%0,%1,%2,%3}, {%4,%5,%6,%7}, {%8,%9}, {%0,%1,%2,%3};\n"
        : "+f"(c[0]), "+f"(c[1]), "+f"(c[2]), "+f"(c[3])
        : "r"(a[0]), "r"(a[1]), "r"(a[2]), "r"(a[3]), "r"(b[0]), "r"(b[1]));
}

__device__ __forceinline__ void ldsm_x4(uint32_t& r0, uint32_t& r1, uint32_t& r2, uint32_t& r3,
                                        uint32_t addr) {
    asm volatile("ldmatrix.sync.aligned.m8n8.x4.shared.b16 {%0,%1,%2,%3}, [%4];"
                 : "=r"(r0), "=r"(r1), "=r"(r2), "=r"(r3) : "r"(addr));
}

__device__ __forceinline__ void ldsm_x4_t(uint32_t& r0, uint32_t& r1, uint32_t& r2, uint32_t& r3,
                                          uint32_t addr) {
    asm volatile("ldmatrix.sync.aligned.m8n8.x4.trans.shared.b16 {%0,%1,%2,%3}, [%4];"
                 : "=r"(r0), "=r"(r1), "=r"(r2), "=r"(r3) : "r"(addr));
}

__device__ __forceinline__ uint32_t smem_u32(const void* p) {
    return (uint32_t)__cvta_generic_to_shared(p);
}

__device__ __forceinline__ void cp_async16(void* smem, const void* gmem) {
    uint32_t s = smem_u32(smem);
    asm volatile("cp.async.cg.shared.global [%0], [%1], 16;\n" :: "r"(s), "l"(gmem));
}
__device__ __forceinline__ void cp_commit() { asm volatile("cp.async.commit_group;\n"); }
template<int N>
__device__ __forceinline__ void cp_wait() { asm volatile("cp.async.wait_group %0;\n" :: "n"(N)); }

// ---------------------------------------------------------------------------
// Pre-round x to fp16
// ---------------------------------------------------------------------------
__global__ void __launch_bounds__(256)
round_fp16(const float* __restrict__ in, __half* __restrict__ out, int n4) {
    int i = blockIdx.x * blockDim.x + threadIdx.x;
    if (i >= n4) return;
    float4 v = ((const float4*)in)[i];
    ((__half2*)out)[2 * i]     = __floats2half2_rn(v.x, v.y);
    ((__half2*)out)[2 * i + 1] = __floats2half2_rn(v.z, v.w);
}

// Transpose + fp16 round: out[n,k] = fp16(in[k,n]); 1024x1024
__global__ void __launch_bounds__(256)
transpose_fp16(const float* __restrict__ in, __half* __restrict__ out) {
    __shared__ float t[32][33];
    int bx = blockIdx.x * 32, by = blockIdx.y * 32;
    int tx = threadIdx.x, ty = threadIdx.y;
    #pragma unroll
    for (int j = 0; j < 32; j += 8)
        t[ty + j][tx] = in[(size_t)(by + ty + j) * DMODEL + bx + tx];
    __syncthreads();
    #pragma unroll
    for (int j = 0; j < 32; j += 8)
        out[(size_t)(bx + ty + j) * DMODEL + by + tx] = __float2half_rn(t[tx][ty + j]);
}

// ---------------------------------------------------------------------------
// FP16 GEMM (m16n8k16, fp32 accumulate), ldmatrix fragments.
// C[M,N] = A[M,K] @ Bt[N,K]^T + bias
// MODE: 0 = plain fp32 out, 3 = softmax fp16 out, 4 = plain fp16 out.
// BATCHED_B: Bt has a separate [N,K] matrix per 4096-row batch of A.
// ---------------------------------------------------------------------------
#define BM 128
#define BN 128
#define BKH 32
#define STAGES 3
#define TSTRH 40

struct SmemPipeH {
    __half As[STAGES][BM][TSTRH];
    __half Bs[STAGES][BN][TSTRH];
};

template<int MODE, bool BATCHED_B>
__global__ void __launch_bounds__(128, 2)
gemm_h(const __half* __restrict__ A, const __half* __restrict__ Bt,
       const float* __restrict__ bias, void* __restrict__ Cv,
       int N, int K) {
    extern __shared__ char smem_raw[];
    SmemPipeH& sp = *reinterpret_cast<SmemPipeH*>(smem_raw);

    float*  Cf = (float*)Cv;
    __half* Ch = (__half*)Cv;

    const int tid  = threadIdx.x;
    const int warp = tid >> 5;
    const int lane = tid & 31;
    const int g  = lane >> 2;
    const int tg = lane & 3;
    const int wm = (warp >> 1) * 64;
    const int wn = (warp & 1) * 64;
    const int bm = blockIdx.y * BM;
    const int bn = blockIdx.x * BN;

    const __half* Bt_use = Bt;
    if (BATCHED_B) Bt_use += (size_t)(bm >> 12) * DMODEL * DMODEL;

    const int a_row  = lane & 15;
    const int a_koff = (lane >> 4) * 8;
    const int b_row  = (lane & 7) + ((lane >> 4) << 3);
    const int b_koff = ((lane >> 3) & 1) * 8;

    const int T = K / BKH;   // 32

    auto load_stage = [&](int kt, int st) {
        #pragma unroll
        for (int i = 0; i < 4; i++) {
            int f = tid + i * 128;
            int r = f >> 2, c = (f & 3) * 8;
            cp_async16(&sp.As[st][r][c], &A[(size_t)(bm + r) * K + kt + c]);
        }
        #pragma unroll
        for (int i = 0; i < 4; i++) {
            int f = tid + i * 128;
            int r = f >> 2, c = (f & 3) * 8;
            cp_async16(&sp.Bs[st][r][c], &Bt_use[(size_t)(bn + r) * K + kt + c]);
        }
        cp_commit();
    };

    float acc[4][8][4] = {};

    load_stage(0, 0);
    load_stage(BKH, 1);

    for (int t = 0; t < T; t++) {
        if (t > 0) __syncthreads();
        if (t + 2 < T) {
            load_stage((t + 2) * BKH, (t + 2) % STAGES);
            cp_wait<2>();
        } else if (t + 1 < T) {
            cp_wait<1>();
        } else {
            cp_wait<0>();
        }
        __syncthreads();

        const int st = t % STAGES;
        #pragma unroll
        for (int k0 = 0; k0 < BKH; k0 += 16) {
            uint32_t af[4][4];
            uint32_t bf[8][2];
            #pragma unroll
            for (int mi = 0; mi < 4; mi++) {
                uint32_t addr = smem_u32(&sp.As[st][wm + mi * 16 + a_row][k0 + a_koff]);
                ldsm_x4(af[mi][0], af[mi][1], af[mi][2], af[mi][3], addr);
            }
            #pragma unroll
            for (int nb = 0; nb < 4; nb++) {
                uint32_t addr = smem_u32(&sp.Bs[st][wn + nb * 16 + b_row][k0 + b_koff]);
                ldsm_x4(bf[2*nb][0], bf[2*nb][1], bf[2*nb+1][0], bf[2*nb+1][1], addr);
            }
            #pragma unroll
            for (int mi = 0; mi < 4; mi++)
                #pragma unroll
                for (int ni = 0; ni < 8; ni++)
                    mma_f16(acc[mi][ni], af[mi], bf[ni]);
        }
    }

    if (MODE == 0 || MODE == 4) {
        #pragma unroll
        for (int mi = 0; mi < 4; mi++) {
            int row = bm + wm + mi * 16 + g;
            #pragma unroll
            for (int ni = 0; ni < 8; ni++) {
                int col = bn + wn + ni * 8 + tg * 2;
                float b0 = bias[col], b1 = bias[col + 1];
                if (MODE == 4) {
                    *(__half2*)&Ch[(size_t)row * N + col] =
                        __floats2half2_rn(acc[mi][ni][0] + b0, acc[mi][ni][1] + b1);
                    *(__half2*)&Ch[(size_t)(row + 8) * N + col] =
                        __floats2half2_rn(acc[mi][ni][2] + b0, acc[mi][ni][3] + b1);
                } else {
                    *(float2*)&Cf[(size_t)row * N + col] =
                        make_float2(acc[mi][ni][0] + b0, acc[mi][ni][1] + b1);
                    *(float2*)&Cf[(size_t)(row + 8) * N + col] =
                        make_float2(acc[mi][ni][2] + b0, acc[mi][ni][3] + b1);
                }
            }
        }
    } else {
        float bia[8][2];
        #pragma unroll
        for (int ni = 0; ni < 8; ni++) {
            int col = bn + wn + ni * 8 + tg * 2;
            bia[ni][0] = bias[col];
            bia[ni][1] = bias[col + 1];
        }
        #pragma unroll
        for (int mi = 0; mi < 4; mi++) {
            #pragma unroll
            for (int j = 0; j < 2; j++) {
                float v[16];
                #pragma unroll
                for (int ni = 0; ni < 8; ni++) {
                    v[2*ni]   = acc[mi][ni][2*j]   + bia[ni][0];
                    v[2*ni+1] = acc[mi][ni][2*j+1] + bia[ni][1];
                }
                float m = v[0];
                #pragma unroll
                for (int i = 1; i < 16; i++) m = fmaxf(m, v[i]);
                m = fmaxf(m, __shfl_xor_sync(0xffffffffu, m, 1));
                m = fmaxf(m, __shfl_xor_sync(0xffffffffu, m, 2));
                float s = 0.f;
                #pragma unroll
                for (int i = 0; i < 16; i++) { v[i] = __expf(v[i] - m); s += v[i]; }
                s += __shfl_xor_sync(0xffffffffu, s, 1);
                s += __shfl_xor_sync(0xffffffffu, s, 2);
                float inv = 1.f / s;
                int row = bm + wm + mi * 16 + g + j * 8;
                #pragma unroll
                for (int ni = 0; ni < 8; ni++) {
                    int col = bn + wn + ni * 8 + tg * 2;
                    *(__half2*)&Ch[(size_t)row * N + col] =
                        __floats2half2_rn(v[2*ni] * inv, v[2*ni+1] * inv);
                }
            }
        }
    }
}

// ---------------------------------------------------------------------------
// Tensor-core KV partials: per CTA, accumulate 4x128-row sub-chunks in-register.
// KVp[chunk,bh,d,e] = sum_{s in 512-chunk} K[s,d]*V[s,e].  Grid (8, 64).
// ---------------------------------------------------------------------------
#define KVSTR 72

__global__ void __launch_bounds__(128)
kv_mma(const __half* __restrict__ Kh, const __half* __restrict__ Vh,
       float* __restrict__ KVp) {
    __shared__ __align__(16) char smem[2 * 128 * KVSTR * 2];   // 36,864 B
    __half (*Ks)[KVSTR] = reinterpret_cast<__half(*)[KVSTR]>(smem);
    __half (*Vs)[KVSTR] = reinterpret_cast<__half(*)[KVSTR]>(smem + 128 * KVSTR * 2);
    float  (*buf)[72]   = reinterpret_cast<float(*)[72]>(smem);

    const int chunk = blockIdx.x;     // 0..7 (512 rows each)
    const int bh = blockIdx.y;
    const int b = bh >> 4, h = bh & 15;
    const int tid = threadIdx.x, warp = tid >> 5, lane = tid & 31;
    const int g = lane >> 2, tg = lane & 3;

    const int a_srow = (lane & 7) + ((lane >> 4) << 3);
    const int a_doff = ((lane >> 3) & 1) * 8;
    const int b_srow = (lane & 7) + (((lane >> 3) & 1) << 3);
    const int b_eoff = (lane >> 4) * 8;

    float acc[4][8][4] = {};

    for (int sub = 0; sub < SUBS; sub++) {
        const size_t rowbase =
            ((size_t)b * SEQ + chunk * (SUBS * 128) + sub * 128) * DMODEL + h * 64;
        #pragma unroll
        for (int i = 0; i < 8; i++) {
            int f = tid + i * 128;
            int r = f >> 3, c = (f & 7) * 8;
            cp_async16(&Ks[r][c], &Kh[rowbase + (size_t)r * DMODEL + c]);
        }
        #pragma unroll
        for (int i = 0; i < 8; i++) {
            int f = tid + i * 128;
            int r = f >> 3, c = (f & 7) * 8;
            cp_async16(&Vs[r][c], &Vh[rowbase + (size_t)r * DMODEL + c]);
        }
        cp_commit(); cp_wait<0>();
        __syncthreads();

        const int s0 = warp * 32;
        #pragma unroll
        for (int ks = 0; ks < 2; ks++) {
            const int sb = s0 + ks * 16;
            uint32_t af[4][4];
            uint32_t bf[8][2];
            #pragma unroll
            for (int mi = 0; mi < 4; mi++) {
                uint32_t addr = smem_u32(&Ks[sb + a_srow][mi * 16 + a_doff]);
                ldsm_x4_t(af[mi][0], af[mi][1], af[mi][2], af[mi][3], addr);
            }
            #pragma unroll
            for (int nb = 0; nb < 4; nb++) {
                uint32_t addr = smem_u32(&Vs[sb + b_srow][nb * 16 + b_eoff]);
                ldsm_x4_t(bf[2*nb][0], bf[2*nb][1], bf[2*nb+1][0], bf[2*nb+1][1], addr);
            }
            #pragma unroll
            for (int mi = 0; mi < 4; mi++)
                #pragma unroll
                for (int ni = 0; ni < 8; ni++)
                    mma_f16(acc[mi][ni], af[mi], bf[ni]);
        }
        __syncthreads();   // tiles consumed before next sub overwrites
    }

    // serial cross-warp accumulate (deterministic); buf aliases the tiles
    for (int w = 0; w < 4; w++) {
        if (warp == w) {
            #pragma unroll
            for (int mi = 0; mi < 4; mi++) {
                #pragma unroll
                for (int ni = 0; ni < 8; ni++) {
                    int r = mi * 16 + g;
                    int c = ni * 8 + tg * 2;
                    if (w == 0) {
                        buf[r][c]       = acc[mi][ni][0];
                        buf[r][c + 1]   = acc[mi][ni][1];
                        buf[r+8][c]     = acc[mi][ni][2];
                        buf[r+8][c + 1] = acc[mi][ni][3];
                    } else {
                        buf[r][c]       += acc[mi][ni][0];
                        buf[r][c + 1]   += acc[mi][ni][1];
                        buf[r+8][c]     += acc[mi][ni][2];
                        buf[r+8][c + 1] += acc[mi][ni][3];
                    }
                }
            }
        }
        __syncthreads();
    }

    float* out = KVp + ((size_t)chunk * BH + bh) * (HDIM * HDIM);
    #pragma unroll
    for (int i = 0; i < 8; i++) {
        int f = tid + i * 128;
        int r = f >> 4, c = (f & 15) * 4;
        float4 v = *(const float4*)&buf[r][c];
        *(float4*)&out[r * 64 + c] = v;
    }
}

__global__ void __launch_bounds__(256)
kv_reduce(const float* __restrict__ KVp, float* __restrict__ KV) {
    int idx = blockIdx.x * blockDim.x + threadIdx.x;
    if (idx >= BH * HDIM * HDIM) return;
    float s = 0.f;
    #pragma unroll
    for (int c = 0; c < KV_CHUNKS; c++)
        s += KVp[(size_t)c * BH * HDIM * HDIM + idx];
    KV[idx] = s;
}

// ---------------------------------------------------------------------------
// Fold Wo into KV:  M_bT[b][n][64h+d] = fp16( sum_e KV[b,h,d,e] * Wo[64h+e, n] )
// ---------------------------------------------------------------------------
__global__ void __launch_bounds__(256)
fold_wo(const float* __restrict__ KV, const float* __restrict__ Wo,
        __half* __restrict__ Mt) {
    __shared__ float KVs[64][65];
    __shared__ float Wos[64][65];
    const int nt = blockIdx.x * 64;
    const int h  = blockIdx.y;
    const int b  = blockIdx.z;
    const int tid = threadIdx.x;

    const float* kvsrc = KV + ((size_t)(b * NHEAD + h)) * (HDIM * HDIM);
    #pragma unroll
    for (int i = 0; i < 4; i++) {
        int f = tid + i * 256;
        int r = f >> 4, c = (f & 15) * 4;
        float4 v = *(const float4*)&kvsrc[r * 64 + c];
        KVs[r][c] = v.x; KVs[r][c+1] = v.y; KVs[r][c+2] = v.z; KVs[r][c+3] = v.w;
    }
    #pragma unroll
    for (int i = 0; i < 4; i++) {
        int f = tid + i * 256;
        int r = f >> 4, c = (f & 15) * 4;
        float4 v = *(const float4*)&Wo[(size_t)(h * 64 + r) * DMODEL + nt + c];
        Wos[r][c] = v.x; Wos[r][c+1] = v.y; Wos[r][c+2] = v.z; Wos[r][c+3] = v.w;
    }
    __syncthreads();

    const int n  = tid >> 2;
    const int d0 = (tid & 3) * 16;
    float acc[16] = {};
    #pragma unroll 8
    for (int e = 0; e < 64; e++) {
        float w = Wos[e][n];
        #pragma unroll
        for (int i = 0; i < 16; i++)
            acc[i] += KVs[d0 + i][e] * w;
    }
    __half* dst = Mt + (size_t)b * DMODEL * DMODEL + (size_t)(nt + n) * DMODEL + h * 64 + d0;
    #pragma unroll
    for (int i = 0; i < 16; i++) dst[i] = __float2half_rn(acc[i]);
}

// ---------------------------------------------------------------------------
// Launch: R12 schedule (best measured). 3 streams, fully-concurrent QKV,
// kv chain on s2 after K/V, monolithic final GEMM on main.
// ---------------------------------------------------------------------------
extern "C" void kernel_launch(void* const* d_in, const int* in_sizes, int n_in,
                              void* d_out, int out_size) {
    const float* x  = (const float*)d_in[0];
    const float* Wq = (const float*)d_in[1];
    const float* bq = (const float*)d_in[2];
    const float* Wk = (const float*)d_in[3];
    const float* bk = (const float*)d_in[4];
    const float* Wv = (const float*)d_in[5];
    const float* bv = (const float*)d_in[6];
    const float* Wo = (const float*)d_in[7];
    const float* bo = (const float*)d_in[8];
    float* out = (float*)d_out;

    __half *X, *W, *Q, *K, *V, *Mt;
    float *KVp, *KV;
    cudaGetSymbolAddress((void**)&X,   g_X);
    cudaGetSymbolAddress((void**)&W,   g_W);
    cudaGetSymbolAddress((void**)&Q,   g_Q);
    cudaGetSymbolAddress((void**)&K,   g_K);
    cudaGetSymbolAddress((void**)&V,   g_V);
    cudaGetSymbolAddress((void**)&KVp, g_KVp);
    cudaGetSymbolAddress((void**)&KV,  g_KV);
    cudaGetSymbolAddress((void**)&Mt,  g_M);

    __half* Wqt = W;
    __half* Wkt = W + (size_t)DMODEL * DMODEL;
    __half* Wvt = W + 2 * (size_t)DMODEL * DMODEL;

    const int smem_bytes = (int)sizeof(SmemPipeH);   // 61,440 B
    static cudaStream_t s2 = nullptr, s3 = nullptr;
    static cudaEvent_t evX = nullptr, evV = nullptr, evM = nullptr;
    if (!s2) {
        cudaFuncSetAttribute(gemm_h<3, false>, cudaFuncAttributeMaxDynamicSharedMemorySize, smem_bytes);
        cudaFuncSetAttribute(gemm_h<4, false>, cudaFuncAttributeMaxDynamicSharedMemorySize, smem_bytes);
        cudaFuncSetAttribute(gemm_h<0, true >, cudaFuncAttributeMaxDynamicSharedMemorySize, smem_bytes);
        int pLeast, pGreatest;
        cudaDeviceGetStreamPriorityRange(&pLeast, &pGreatest);
        cudaStreamCreateWithPriority(&s2, cudaStreamNonBlocking, pGreatest);
        cudaStreamCreateWithPriority(&s3, cudaStreamNonBlocking, pGreatest);
        cudaEventCreateWithFlags(&evX, cudaEventDisableTiming);
        cudaEventCreateWithFlags(&evV, cudaEventDisableTiming);
        cudaEventCreateWithFlags(&evM, cudaEventDisableTiming);
    }

    dim3 tgrid(32, 32), tblk(32, 8);
    dim3 ggrid(DMODEL / BN, MROWS / BM);   // (8, 128)
    const int n4x = MROWS * DMODEL / 4;

    // prologue, spread across streams
    round_fp16<<<(n4x + 255) / 256, 256>>>(x, X, n4x);
    cudaEventRecord(evX, 0);
    transpose_fp16<<<tgrid, tblk, 0, s2>>>(Wk, Wkt);
    transpose_fp16<<<tgrid, tblk, 0, s3>>>(Wv, Wvt);
    transpose_fp16<<<tgrid, tblk>>>(Wq, Wqt);

    // K GEMM on s2, V GEMM on s3, Q GEMM on main — fully concurrent
    cudaStreamWaitEvent(s2, evX, 0);
    gemm_h<3, false><<<ggrid, 128, smem_bytes, s2>>>(X, Wkt, bk, K, DMODEL, DMODEL);

    cudaStreamWaitEvent(s3, evX, 0);
    gemm_h<4, false><<<ggrid, 128, smem_bytes, s3>>>(X, Wvt, bv, V, DMODEL, DMODEL);
    cudaEventRecord(evV, s3);

    gemm_h<3, false><<<ggrid, 128, smem_bytes>>>(X, Wqt, bq, Q, DMODEL, DMODEL);

    // kv chain on s2 (after K via stream order, V via event)
    cudaStreamWaitEvent(s2, evV, 0);
    kv_mma<<<dim3(KV_CHUNKS, BH), 128, 0, s2>>>(K, V, KVp);
    kv_reduce<<<(BH * HDIM * HDIM + 255) / 256, 256, 0, s2>>>(KVp, KV);
    fold_wo<<<dim3(16, NHEAD, BATCH), 256, 0, s2>>>(KV, Wo, Mt);
    cudaEventRecord(evM, s2);

    // join: final batched GEMM needs Q (main-stream order) + Mt
    cudaStreamWaitEvent(0, evM, 0);
    gemm_h<0, true><<<ggrid, 128, smem_bytes>>>(Q, Mt, bo, out, DMODEL, DMODEL);
}

// round 17
// speedup vs baseline: 1.1711x; 1.0081x over previous
#include <cuda_runtime.h>
#include <cuda_fp16.h>
#include <cstdint>

// Problem constants
#define BATCH 4
#define SEQ 4096
#define DMODEL 1024
#define NHEAD 16
#define HDIM 64
#define MROWS (BATCH * SEQ)        // 16384
#define BH (BATCH * NHEAD)         // 64
#define KV_CHUNKS 8                // 512-row chunks per batch
#define SUBS 4                     // 128-row sub-chunks per chunk

// Scratch (device globals; no cudaMalloc allowed)
__device__ __half g_X[MROWS * DMODEL];
__device__ __half g_W[3][DMODEL * DMODEL];       // fp16, TRANSPOSED Wq,Wk,Wv [n,k]
__device__ __half g_Q[MROWS * DMODEL];
__device__ __half g_K[MROWS * DMODEL];
__device__ __half g_V[MROWS * DMODEL];
__device__ float  g_KVp[KV_CHUNKS * BH * HDIM * HDIM];
__device__ float  g_KV[BH * HDIM * HDIM];
__device__ __half g_M[BATCH * DMODEL * DMODEL];  // M_bT[b][n][dh], fp16

// ---------------------------------------------------------------------------
// Helpers
// ---------------------------------------------------------------------------
__device__ __forceinline__ void mma_f16(float c[4], const uint32_t a[4], const uint32_t b[2]) {
    asm volatile(
        "mma.sync.aligned.m16n8k16.row.col.f32.f16.f16.f32 "
        "{%0,%1,%2,%3}, {%4,%5,%6,%7}, {%8,%9}, {%0,%1,%2,%3};\n"
        : "+f"(c[0]), "+f"(c[1]), "+f"(c[2]), "+f"(c[3])
        : "r"(a[0]), "r"(a[1]), "r"(a[2]), "r"(a[3]), "r"(b[0]), "r"(b[1]));
}

__device__ __forceinline__ void ldsm_x4(uint32_t& r0, uint32_t& r1, uint32_t& r2, uint32_t& r3,
                                        uint32_t addr) {
    asm volatile("ldmatrix.sync.aligned.m8n8.x4.shared.b16 {%0,%1,%2,%3}, [%4];"
                 : "=r"(r0), "=r"(r1), "=r"(r2), "=r"(r3) : "r"(addr));
}

__device__ __forceinline__ void ldsm_x4_t(uint32_t& r0, uint32_t& r1, uint32_t& r2, uint32_t& r3,
                                          uint32_t addr) {
    asm volatile("ldmatrix.sync.aligned.m8n8.x4.trans.shared.b16 {%0,%1,%2,%3}, [%4];"
                 : "=r"(r0), "=r"(r1), "=r"(r2), "=r"(r3) : "r"(addr));
}

__device__ __forceinline__ uint32_t smem_u32(const void* p) {
    return (uint32_t)__cvta_generic_to_shared(p);
}

__device__ __forceinline__ void cp_async16(void* smem, const void* gmem) {
    uint32_t s = smem_u32(smem);
    asm volatile("cp.async.cg.shared.global [%0], [%1], 16;\n" :: "r"(s), "l"(gmem));
}
__device__ __forceinline__ void cp_commit() { asm volatile("cp.async.commit_group;\n"); }
template<int N>
__device__ __forceinline__ void cp_wait() { asm volatile("cp.async.wait_group %0;\n" :: "n"(N)); }

// ---------------------------------------------------------------------------
// Pre-round x to fp16
// ---------------------------------------------------------------------------
__global__ void __launch_bounds__(256)
round_fp16(const float* __restrict__ in, __half* __restrict__ out, int n4) {
    int i = blockIdx.x * blockDim.x + threadIdx.x;
    if (i >= n4) return;
    float4 v = ((const float4*)in)[i];
    ((__half2*)out)[2 * i]     = __floats2half2_rn(v.x, v.y);
    ((__half2*)out)[2 * i + 1] = __floats2half2_rn(v.z, v.w);
}

// Transpose + fp16 round: out[n,k] = fp16(in[k,n]); 1024x1024
__global__ void __launch_bounds__(256)
transpose_fp16(const float* __restrict__ in, __half* __restrict__ out) {
    __shared__ float t[32][33];
    int bx = blockIdx.x * 32, by = blockIdx.y * 32;
    int tx = threadIdx.x, ty = threadIdx.y;
    #pragma unroll
    for (int j = 0; j < 32; j += 8)
        t[ty + j][tx] = in[(size_t)(by + ty + j) * DMODEL + bx + tx];
    __syncthreads();
    #pragma unroll
    for (int j = 0; j < 32; j += 8)
        out[(size_t)(bx + ty + j) * DMODEL + by + tx] = __float2half_rn(t[tx][ty + j]);
}

// ---------------------------------------------------------------------------
// FP16 GEMM (m16n8k16, fp32 accumulate), ldmatrix fragments.
// C[M,N] = A[M,K] @ Bt[N,K]^T + bias
// MODE: 0 = plain fp32 out, 3 = softmax fp16 out, 4 = plain fp16 out.
// BATCHED_B: Bt has a separate [N,K] matrix per 4096-row batch of A.
// ---------------------------------------------------------------------------
#define BM 128
#define BN 128
#define BKH 32
#define STAGES 3
#define TSTRH 40

struct SmemPipeH {
    __half As[STAGES][BM][TSTRH];
    __half Bs[STAGES][BN][TSTRH];
};

template<int MODE, bool BATCHED_B>
__global__ void __launch_bounds__(128, 2)
gemm_h(const __half* __restrict__ A, const __half* __restrict__ Bt,
       const float* __restrict__ bias, void* __restrict__ Cv,
       int N, int K) {
    extern __shared__ char smem_raw[];
    SmemPipeH& sp = *reinterpret_cast<SmemPipeH*>(smem_raw);

    float*  Cf = (float*)Cv;
    __half* Ch = (__half*)Cv;

    const int tid  = threadIdx.x;
    const int warp = tid >> 5;
    const int lane = tid & 31;
    const int g  = lane >> 2;
    const int tg = lane & 3;
    const int wm = (warp >> 1) * 64;
    const int wn = (warp & 1) * 64;
    const int bm = blockIdx.y * BM;
    const int bn = blockIdx.x * BN;

    const __half* Bt_use = Bt;
    if (BATCHED_B) Bt_use += (size_t)(bm >> 12) * DMODEL * DMODEL;

    const int a_row  = lane & 15;
    const int a_koff = (lane >> 4) * 8;
    const int b_row  = (lane & 7) + ((lane >> 4) << 3);
    const int b_koff = ((lane >> 3) & 1) * 8;

    const int T = K / BKH;   // 32

    auto load_stage = [&](int kt, int st) {
        #pragma unroll
        for (int i = 0; i < 4; i++) {
            int f = tid + i * 128;
            int r = f >> 2, c = (f & 3) * 8;
            cp_async16(&sp.As[st][r][c], &A[(size_t)(bm + r) * K + kt + c]);
        }
        #pragma unroll
        for (int i = 0; i < 4; i++) {
            int f = tid + i * 128;
            int r = f >> 2, c = (f & 3) * 8;
            cp_async16(&sp.Bs[st][r][c], &Bt_use[(size_t)(bn + r) * K + kt + c]);
        }
        cp_commit();
    };

    float acc[4][8][4] = {};

    load_stage(0, 0);
    load_stage(BKH, 1);

    for (int t = 0; t < T; t++) {
        if (t > 0) __syncthreads();
        if (t + 2 < T) {
            load_stage((t + 2) * BKH, (t + 2) % STAGES);
            cp_wait<2>();
        } else if (t + 1 < T) {
            cp_wait<1>();
        } else {
            cp_wait<0>();
        }
        __syncthreads();

        const int st = t % STAGES;
        #pragma unroll
        for (int k0 = 0; k0 < BKH; k0 += 16) {
            uint32_t af[4][4];
            uint32_t bf[8][2];
            #pragma unroll
            for (int mi = 0; mi < 4; mi++) {
                uint32_t addr = smem_u32(&sp.As[st][wm + mi * 16 + a_row][k0 + a_koff]);
                ldsm_x4(af[mi][0], af[mi][1], af[mi][2], af[mi][3], addr);
            }
            #pragma unroll
            for (int nb = 0; nb < 4; nb++) {
                uint32_t addr = smem_u32(&sp.Bs[st][wn + nb * 16 + b_row][k0 + b_koff]);
                ldsm_x4(bf[2*nb][0], bf[2*nb][1], bf[2*nb+1][0], bf[2*nb+1][1], addr);
            }
            #pragma unroll
            for (int mi = 0; mi < 4; mi++)
                #pragma unroll
                for (int ni = 0; ni < 8; ni++)
                    mma_f16(acc[mi][ni], af[mi], bf[ni]);
        }
    }

    if (MODE == 0 || MODE == 4) {
        #pragma unroll
        for (int mi = 0; mi < 4; mi++) {
            int row = bm + wm + mi * 16 + g;
            #pragma unroll
            for (int ni = 0; ni < 8; ni++) {
                int col = bn + wn + ni * 8 + tg * 2;
                float b0 = bias[col], b1 = bias[col + 1];
                if (MODE == 4) {
                    *(__half2*)&Ch[(size_t)row * N + col] =
                        __floats2half2_rn(acc[mi][ni][0] + b0, acc[mi][ni][1] + b1);
                    *(__half2*)&Ch[(size_t)(row + 8) * N + col] =
                        __floats2half2_rn(acc[mi][ni][2] + b0, acc[mi][ni][3] + b1);
                } else {
                    *(float2*)&Cf[(size_t)row * N + col] =
                        make_float2(acc[mi][ni][0] + b0, acc[mi][ni][1] + b1);
                    *(float2*)&Cf[(size_t)(row + 8) * N + col] =
                        make_float2(acc[mi][ni][2] + b0, acc[mi][ni][3] + b1);
                }
            }
        }
    } else {
        float bia[8][2];
        #pragma unroll
        for (int ni = 0; ni < 8; ni++) {
            int col = bn + wn + ni * 8 + tg * 2;
            bia[ni][0] = bias[col];
            bia[ni][1] = bias[col + 1];
        }
        #pragma unroll
        for (int mi = 0; mi < 4; mi++) {
            #pragma unroll
            for (int j = 0; j < 2; j++) {
                float v[16];
                #pragma unroll
                for (int ni = 0; ni < 8; ni++) {
                    v[2*ni]   = acc[mi][ni][2*j]   + bia[ni][0];
                    v[2*ni+1] = acc[mi][ni][2*j+1] + bia[ni][1];
                }
                float m = v[0];
                #pragma unroll
                for (int i = 1; i < 16; i++) m = fmaxf(m, v[i]);
                m = fmaxf(m, __shfl_xor_sync(0xffffffffu, m, 1));
                m = fmaxf(m, __shfl_xor_sync(0xffffffffu, m, 2));
                float s = 0.f;
                #pragma unroll
                for (int i = 0; i < 16; i++) { v[i] = __expf(v[i] - m); s += v[i]; }
                s += __shfl_xor_sync(0xffffffffu, s, 1);
                s += __shfl_xor_sync(0xffffffffu, s, 2);
                float inv = 1.f / s;
                int row = bm + wm + mi * 16 + g + j * 8;
                #pragma unroll
                for (int ni = 0; ni < 8; ni++) {
                    int col = bn + wn + ni * 8 + tg * 2;
                    *(__half2*)&Ch[(size_t)row * N + col] =
                        __floats2half2_rn(v[2*ni] * inv, v[2*ni+1] * inv);
                }
            }
        }
    }
}

// ---------------------------------------------------------------------------
// Tensor-core KV partials: per CTA, 4x128-row sub-chunks in-register.
// Grid (KV_CHUNKS, nbh); bh = blockIdx.y + bh0.
// ---------------------------------------------------------------------------
#define KVSTR 72

__global__ void __launch_bounds__(128)
kv_mma(const __half* __restrict__ Kh, const __half* __restrict__ Vh,
       float* __restrict__ KVp, int bh0) {
    __shared__ __align__(16) char smem[2 * 128 * KVSTR * 2];   // 36,864 B
    __half (*Ks)[KVSTR] = reinterpret_cast<__half(*)[KVSTR]>(smem);
    __half (*Vs)[KVSTR] = reinterpret_cast<__half(*)[KVSTR]>(smem + 128 * KVSTR * 2);
    float  (*buf)[72]   = reinterpret_cast<float(*)[72]>(smem);

    const int chunk = blockIdx.x;     // 0..7 (512 rows each)
    const int bh = blockIdx.y + bh0;
    const int b = bh >> 4, h = bh & 15;
    const int tid = threadIdx.x, warp = tid >> 5, lane = tid & 31;
    const int g = lane >> 2, tg = lane & 3;

    const int a_srow = (lane & 7) + ((lane >> 4) << 3);
    const int a_doff = ((lane >> 3) & 1) * 8;
    const int b_srow = (lane & 7) + (((lane >> 3) & 1) << 3);
    const int b_eoff = (lane >> 4) * 8;

    float acc[4][8][4] = {};

    for (int sub = 0; sub < SUBS; sub++) {
        const size_t rowbase =
            ((size_t)b * SEQ + chunk * (SUBS * 128) + sub * 128) * DMODEL + h * 64;
        #pragma unroll
        for (int i = 0; i < 8; i++) {
            int f = tid + i * 128;
            int r = f >> 3, c = (f & 7) * 8;
            cp_async16(&Ks[r][c], &Kh[rowbase + (size_t)r * DMODEL + c]);
        }
        #pragma unroll
        for (int i = 0; i < 8; i++) {
            int f = tid + i * 128;
            int r = f >> 3, c = (f & 7) * 8;
            cp_async16(&Vs[r][c], &Vh[rowbase + (size_t)r * DMODEL + c]);
        }
        cp_commit(); cp_wait<0>();
        __syncthreads();

        const int s0 = warp * 32;
        #pragma unroll
        for (int ks = 0; ks < 2; ks++) {
            const int sb = s0 + ks * 16;
            uint32_t af[4][4];
            uint32_t bf[8][2];
            #pragma unroll
            for (int mi = 0; mi < 4; mi++) {
                uint32_t addr = smem_u32(&Ks[sb + a_srow][mi * 16 + a_doff]);
                ldsm_x4_t(af[mi][0], af[mi][1], af[mi][2], af[mi][3], addr);
            }
            #pragma unroll
            for (int nb = 0; nb < 4; nb++) {
                uint32_t addr = smem_u32(&Vs[sb + b_srow][nb * 16 + b_eoff]);
                ldsm_x4_t(bf[2*nb][0], bf[2*nb][1], bf[2*nb+1][0], bf[2*nb+1][1], addr);
            }
            #pragma unroll
            for (int mi = 0; mi < 4; mi++)
                #pragma unroll
                for (int ni = 0; ni < 8; ni++)
                    mma_f16(acc[mi][ni], af[mi], bf[ni]);
        }
        __syncthreads();
    }

    // serial cross-warp accumulate (deterministic); buf aliases the tiles
    for (int w = 0; w < 4; w++) {
        if (warp == w) {
            #pragma unroll
            for (int mi = 0; mi < 4; mi++) {
                #pragma unroll
                for (int ni = 0; ni < 8; ni++) {
                    int r = mi * 16 + g;
                    int c = ni * 8 + tg * 2;
                    if (w == 0) {
                        buf[r][c]       = acc[mi][ni][0];
                        buf[r][c + 1]   = acc[mi][ni][1];
                        buf[r+8][c]     = acc[mi][ni][2];
                        buf[r+8][c + 1] = acc[mi][ni][3];
                    } else {
                        buf[r][c]       += acc[mi][ni][0];
                        buf[r][c + 1]   += acc[mi][ni][1];
                        buf[r+8][c]     += acc[mi][ni][2];
                        buf[r+8][c + 1] += acc[mi][ni][3];
                    }
                }
            }
        }
        __syncthreads();
    }

    float* out = KVp + ((size_t)chunk * BH + bh) * (HDIM * HDIM);
    #pragma unroll
    for (int i = 0; i < 8; i++) {
        int f = tid + i * 128;
        int r = f >> 4, c = (f & 15) * 4;
        float4 v = *(const float4*)&buf[r][c];
        *(float4*)&out[r * 64 + c] = v;
    }
}

// reduce over chunks for bh in [bh0, bh0+nbh)
__global__ void __launch_bounds__(256)
kv_reduce(const float* __restrict__ KVp, float* __restrict__ KV, int bh0, int nbh) {
    int idx = blockIdx.x * blockDim.x + threadIdx.x;
    if (idx >= nbh * HDIM * HDIM) return;
    int gidx = bh0 * HDIM * HDIM + idx;
    float s = 0.f;
    #pragma unroll
    for (int c = 0; c < KV_CHUNKS; c++)
        s += KVp[(size_t)c * BH * HDIM * HDIM + gidx];
    KV[gidx] = s;
}

// ---------------------------------------------------------------------------
// Fold Wo into KV for batches [b0, b0+gridDim.z)
// ---------------------------------------------------------------------------
__global__ void __launch_bounds__(256)
fold_wo(const float* __restrict__ KV, const float* __restrict__ Wo,
        __half* __restrict__ Mt, int b0) {
    __shared__ float KVs[64][65];
    __shared__ float Wos[64][65];
    const int nt = blockIdx.x * 64;
    const int h  = blockIdx.y;
    const int b  = blockIdx.z + b0;
    const int tid = threadIdx.x;

    const float* kvsrc = KV + ((size_t)(b * NHEAD + h)) * (HDIM * HDIM);
    #pragma unroll
    for (int i = 0; i < 4; i++) {
        int f = tid + i * 256;
        int r = f >> 4, c = (f & 15) * 4;
        float4 v = *(const float4*)&kvsrc[r * 64 + c];
        KVs[r][c] = v.x; KVs[r][c+1] = v.y; KVs[r][c+2] = v.z; KVs[r][c+3] = v.w;
    }
    #pragma unroll
    for (int i = 0; i < 4; i++) {
        int f = tid + i * 256;
        int r = f >> 4, c = (f & 15) * 4;
        float4 v = *(const float4*)&Wo[(size_t)(h * 64 + r) * DMODEL + nt + c];
        Wos[r][c] = v.x; Wos[r][c+1] = v.y; Wos[r][c+2] = v.z; Wos[r][c+3] = v.w;
    }
    __syncthreads();

    const int n  = tid >> 2;
    const int d0 = (tid & 3) * 16;
    float acc[16] = {};
    #pragma unroll 8
    for (int e = 0; e < 64; e++) {
        float w = Wos[e][n];
        #pragma unroll
        for (int i = 0; i < 16; i++)
            acc[i] += KVs[d0 + i][e] * w;
    }
    __half* dst = Mt + (size_t)b * DMODEL * DMODEL + (size_t)(nt + n) * DMODEL + h * 64 + d0;
    #pragma unroll
    for (int i = 0; i < 16; i++) dst[i] = __float2half_rn(acc[i]);
}

// ---------------------------------------------------------------------------
// Launch: R15 skeleton (prologue + projections identical); kv chain split
// into two independent bh-halves on s2 and s3 (both already capture-rooted).
// ---------------------------------------------------------------------------
extern "C" void kernel_launch(void* const* d_in, const int* in_sizes, int n_in,
                              void* d_out, int out_size) {
    const float* x  = (const float*)d_in[0];
    const float* Wq = (const float*)d_in[1];
    const float* bq = (const float*)d_in[2];
    const float* Wk = (const float*)d_in[3];
    const float* bk = (const float*)d_in[4];
    const float* Wv = (const float*)d_in[5];
    const float* bv = (const float*)d_in[6];
    const float* Wo = (const float*)d_in[7];
    const float* bo = (const float*)d_in[8];
    float* out = (float*)d_out;

    __half *X, *W, *Q, *K, *V, *Mt;
    float *KVp, *KV;
    cudaGetSymbolAddress((void**)&X,   g_X);
    cudaGetSymbolAddress((void**)&W,   g_W);
    cudaGetSymbolAddress((void**)&Q,   g_Q);
    cudaGetSymbolAddress((void**)&K,   g_K);
    cudaGetSymbolAddress((void**)&V,   g_V);
    cudaGetSymbolAddress((void**)&KVp, g_KVp);
    cudaGetSymbolAddress((void**)&KV,  g_KV);
    cudaGetSymbolAddress((void**)&Mt,  g_M);

    __half* Wqt = W;
    __half* Wkt = W + (size_t)DMODEL * DMODEL;
    __half* Wvt = W + 2 * (size_t)DMODEL * DMODEL;

    const int smem_bytes = (int)sizeof(SmemPipeH);   // 61,440 B
    static cudaStream_t s2 = nullptr, s3 = nullptr;
    static cudaEvent_t evX, evK, evV, evM1, evM2;
    if (!s2) {
        cudaFuncSetAttribute(gemm_h<3, false>, cudaFuncAttributeMaxDynamicSharedMemorySize, smem_bytes);
        cudaFuncSetAttribute(gemm_h<4, false>, cudaFuncAttributeMaxDynamicSharedMemorySize, smem_bytes);
        cudaFuncSetAttribute(gemm_h<0, true >, cudaFuncAttributeMaxDynamicSharedMemorySize, smem_bytes);
        int pLeast, pGreatest;
        cudaDeviceGetStreamPriorityRange(&pLeast, &pGreatest);
        cudaStreamCreateWithPriority(&s2, cudaStreamNonBlocking, pGreatest);
        cudaStreamCreateWithPriority(&s3, cudaStreamNonBlocking, pGreatest);
        cudaEventCreateWithFlags(&evX,  cudaEventDisableTiming);
        cudaEventCreateWithFlags(&evK,  cudaEventDisableTiming);
        cudaEventCreateWithFlags(&evV,  cudaEventDisableTiming);
        cudaEventCreateWithFlags(&evM1, cudaEventDisableTiming);
        cudaEventCreateWithFlags(&evM2, cudaEventDisableTiming);
    }

    dim3 tgrid(32, 32), tblk(32, 8);
    dim3 ggrid(DMODEL / BN, MROWS / BM);   // (8, 128)
    const int n4x = MROWS * DMODEL / 4;

    // prologue (identical to R15): round X on main, transposes spread
    round_fp16<<<(n4x + 255) / 256, 256>>>(x, X, n4x);
    cudaEventRecord(evX, 0);
    transpose_fp16<<<tgrid, tblk, 0, s2>>>(Wk, Wkt);
    transpose_fp16<<<tgrid, tblk, 0, s3>>>(Wv, Wvt);
    transpose_fp16<<<tgrid, tblk>>>(Wq, Wqt);

    // K GEMM on s2, V GEMM on s3, Q GEMM on main — fully concurrent
    cudaStreamWaitEvent(s2, evX, 0);
    gemm_h<3, false><<<ggrid, 128, smem_bytes, s2>>>(X, Wkt, bk, K, DMODEL, DMODEL);
    cudaEventRecord(evK, s2);

    cudaStreamWaitEvent(s3, evX, 0);
    gemm_h<4, false><<<ggrid, 128, smem_bytes, s3>>>(X, Wvt, bv, V, DMODEL, DMODEL);
    cudaEventRecord(evV, s3);

    gemm_h<3, false><<<ggrid, 128, smem_bytes>>>(X, Wqt, bq, Q, DMODEL, DMODEL);

    // kv chain split: bh 0-31 on s2 (after K in-order + V via event),
    //                 bh 32-63 on s3 (after V in-order + K via event)
    cudaStreamWaitEvent(s2, evV, 0);
    kv_mma<<<dim3(KV_CHUNKS, 32), 128, 0, s2>>>(K, V, KVp, 0);
    kv_reduce<<<(32 * HDIM * HDIM + 255) / 256, 256, 0, s2>>>(KVp, KV, 0, 32);
    fold_wo<<<dim3(16, NHEAD, 2), 256, 0, s2>>>(KV, Wo, Mt, 0);
    cudaEventRecord(evM1, s2);

    cudaStreamWaitEvent(s3, evK, 0);
    kv_mma<<<dim3(KV_CHUNKS, 32), 128, 0, s3>>>(K, V, KVp, 32);
    kv_reduce<<<(32 * HDIM * HDIM + 255) / 256, 256, 0, s3>>>(KVp, KV, 32, 32);
    fold_wo<<<dim3(16, NHEAD, 2), 256, 0, s3>>>(KV, Wo, Mt, 2);
    cudaEventRecord(evM2, s3);

    // join: final batched GEMM needs Q (main-stream order) + both Mt halves
    cudaStreamWaitEvent(0, evM1, 0);
    cudaStreamWaitEvent(0, evM2, 0);
    gemm_h<0, true><<<ggrid, 128, smem_bytes>>>(Q, Mt, bo, out, DMODEL, DMODEL);
}